// round 6
// baseline (speedup 1.0000x reference)
#include <cuda_runtime.h>
#include <math.h>

#define BB 4
#define SS 1024
#define HID 768
#define HH 6
#define DD 64
#define AH 384
#define KSZ 9
#define PADW 4
#define MROWS (BB*SS)

// ---------------- scratch (device globals; no allocation) ----------------
__device__ float g_mq[MROWS*AH];
__device__ float g_mk[MROWS*AH];
__device__ float g_mv[MROWS*AH];
__device__ float g_co[MROWS*AH];
__device__ float g_mkc[MROWS*AH];
__device__ float g_dw[MROWS*HID];
__device__ float g_pwT[HID*AH];
__device__ float g_ck[MROWS*HH*KSZ];
__device__ float g_tdsm[BB*SS];

// ---------------- transpose pw_w (AH,HID) -> (HID,AH) ----------------
__global__ void transpose_pw_kernel(const float* __restrict__ pw) {
    int idx = blockIdx.x * 256 + threadIdx.x;
    if (idx < AH * HID) {
        int o = idx / HID, c = idx % HID;
        g_pwT[c * AH + o] = pw[idx];
    }
}

// ---------------- depthwise conv over sequence dim of K ----------------
__global__ void dw_kernel(const float* __restrict__ Kin, const float* __restrict__ dww) {
    int idx = blockIdx.x * 256 + threadIdx.x;
    if (idx >= MROWS * HID) return;
    int c = idx % HID;
    int m = idx / HID;
    int s = m % SS;
    int b = m / SS;
    float acc = 0.f;
#pragma unroll
    for (int k = 0; k < KSZ; k++) {
        int sp = s + k - PADW;
        if (sp >= 0 && sp < SS)
            acc += Kin[(size_t)(b * SS + sp) * HID + c] * dww[c * KSZ + k];
    }
    g_dw[idx] = acc;
}

// ---------------- SGEMM NN: C[M,N] = A[M,K] @ B[K,N] (+bias) ----------------
// BM=BN=64, BK=16, 256 threads, 4x4 micro-tile
__global__ void sgemm_kernel(const float* __restrict__ A, const float* __restrict__ Bm,
                             const float* __restrict__ bias, float* __restrict__ C,
                             int M, int N, int Kd) {
    __shared__ float As[16][64];
    __shared__ float Bs[16][64];
    int tid = threadIdx.x;
    int tx = tid & 15, ty = tid >> 4;
    int n0 = blockIdx.x * 64, m0 = blockIdx.y * 64;
    int arow = tid >> 2, ak4 = tid & 3;
    int bk = tid >> 4, bc4 = tid & 15;
    float acc[4][4];
#pragma unroll
    for (int i = 0; i < 4; i++)
#pragma unroll
        for (int j = 0; j < 4; j++) acc[i][j] = 0.f;

    for (int k0 = 0; k0 < Kd; k0 += 16) {
        float4 av = *(const float4*)(A + (size_t)(m0 + arow) * Kd + k0 + ak4 * 4);
        As[ak4 * 4 + 0][arow] = av.x;
        As[ak4 * 4 + 1][arow] = av.y;
        As[ak4 * 4 + 2][arow] = av.z;
        As[ak4 * 4 + 3][arow] = av.w;
        float4 bv = *(const float4*)(Bm + (size_t)(k0 + bk) * N + n0 + bc4 * 4);
        *(float4*)&Bs[bk][bc4 * 4] = bv;
        __syncthreads();
#pragma unroll
        for (int kk = 0; kk < 16; kk++) {
            float a[4], bb[4];
#pragma unroll
            for (int i = 0; i < 4; i++) a[i] = As[kk][ty * 4 + i];
#pragma unroll
            for (int j = 0; j < 4; j++) bb[j] = Bs[kk][tx * 4 + j];
#pragma unroll
            for (int i = 0; i < 4; i++)
#pragma unroll
                for (int j = 0; j < 4; j++) acc[i][j] += a[i] * bb[j];
        }
        __syncthreads();
    }
#pragma unroll
    for (int i = 0; i < 4; i++) {
        int row = m0 + ty * 4 + i;
#pragma unroll
        for (int j = 0; j < 4; j++) {
            int col = n0 + tx * 4 + j;
            float v = acc[i][j];
            if (bias) v += bias[col];
            C[(size_t)row * N + col] = v;
        }
    }
}

// ---------------- ck = softmax over KS of (mkc*mq) @ ck_W + ck_b ----------------
__global__ void ck_kernel(const float* __restrict__ ckW, const float* __restrict__ ckb) {
    __shared__ float arow[AH];
    __shared__ float lg[HH * KSZ];
    int m = blockIdx.x;
    int tid = threadIdx.x; // 64 threads
    for (int x = tid; x < AH; x += 64)
        arow[x] = g_mkc[(size_t)m * AH + x] * g_mq[(size_t)m * AH + x];
    __syncthreads();
    if (tid < HH * KSZ) {
        float acc = ckb[tid];
        for (int c = 0; c < AH; c++) acc += arow[c] * ckW[c * (HH * KSZ) + tid];
        lg[tid] = acc;
    }
    __syncthreads();
    if (tid < HH) {
        float mx = -3.0e38f;
#pragma unroll
        for (int k = 0; k < KSZ; k++) mx = fmaxf(mx, lg[tid * KSZ + k]);
        float e[KSZ], sum = 0.f;
#pragma unroll
        for (int k = 0; k < KSZ; k++) { e[k] = expf(lg[tid * KSZ + k] - mx); sum += e[k]; }
        float inv = 1.0f / sum;
#pragma unroll
        for (int k = 0; k < KSZ; k++)
            g_ck[(size_t)m * (HH * KSZ) + tid * KSZ + k] = e[k] * inv;
    }
}

// ---------------- conv_out: dynamic-kernel gather over co ----------------
__global__ void convout_kernel(float* __restrict__ out) {
    int idx = blockIdx.x * 256 + threadIdx.x;
    if (idx >= BB * SS * HH * DD) return;
    int d = idx & 63;
    int h = (idx >> 6) % HH;
    int s = (idx / (DD * HH)) % SS;
    int b = idx / (DD * HH * SS);
    const float* ckp = g_ck + ((size_t)(b * SS + s) * HH + h) * KSZ;
    float acc = 0.f;
#pragma unroll
    for (int k = 0; k < KSZ; k++) {
        int sp = s + k - PADW;
        if (sp >= 0 && sp < SS)
            acc += g_co[(size_t)(b * SS + sp) * AH + h * DD + d] * ckp[k];
    }
    out[(size_t)(b * SS + s) * (2 * AH) + AH + h * DD + d] = acc;
}

// ---------------- td_sm precompute (per batch) ----------------
__global__ void tdsm_kernel(const float* __restrict__ td, const int* __restrict__ mask) {
    __shared__ float red[256];
    int b = blockIdx.x;
    int tid = threadIdx.x;
    float tv[4];
    float ssq = 0.f;
#pragma unroll
    for (int u = 0; u < 4; u++) {
        tv[u] = td[b * SS + tid * 4 + u];
        ssq += tv[u] * tv[u];
    }
    red[tid] = ssq;
    __syncthreads();
    for (int o = 128; o > 0; o >>= 1) {
        if (tid < o) red[tid] += red[tid + o];
        __syncthreads();
    }
    float denom = fmaxf(sqrtf(red[0]), 1e-12f);
    __syncthreads();
    int ms[4];
    float mv[4];
    float lmax = -3.0e38f;
#pragma unroll
    for (int u = 0; u < 4; u++) {
        ms[u] = mask[b * SS + tid * 4 + u];
        mv[u] = ms[u] ? (tv[u] / denom) : -1e4f;
        lmax = fmaxf(lmax, mv[u]);
    }
    red[tid] = lmax;
    __syncthreads();
    for (int o = 128; o > 0; o >>= 1) {
        if (tid < o) red[tid] = fmaxf(red[tid], red[tid + o]);
        __syncthreads();
    }
    float rmax = red[0];
    __syncthreads();
    float e[4], lsum = 0.f;
#pragma unroll
    for (int u = 0; u < 4; u++) {
        e[u] = ms[u] ? expf(mv[u] - rmax) : 0.f;
        lsum += e[u];
    }
    red[tid] = lsum;
    __syncthreads();
    for (int o = 128; o > 0; o >>= 1) {
        if (tid < o) red[tid] += red[tid + o];
        __syncthreads();
    }
    float invZ = 1.0f / red[0];
#pragma unroll
    for (int u = 0; u < 4; u++)
        g_tdsm[b * SS + tid * 4 + u] = e[u] * invZ;
}

// ---------------- fused attention ----------------
#define TJ 256
#define TI 4
#define KTS 65

__global__ void attn_kernel(const int* __restrict__ mask, const float* __restrict__ gammas,
                            float* __restrict__ out) {
    extern __shared__ float sm[];
    float* kt = sm;                 // TJ*KTS = 16640
    float* sbuf = kt + TJ * KTS;    // TI*SS  = 4096
    float* qs = sbuf + TI * SS;     // TI*DD  = 256
    float* red = qs + TI * DD;      // 256
    float* scn = red + 256;         // 256
    float* cbuf = scn + 256;        // 256

    const int tid = threadIdx.x;
    const int it = blockIdx.x % (SS / TI);
    const int bh = blockIdx.x / (SS / TI);
    const int h = bh % HH;
    const int b = bh / HH;
    const int i0 = it * TI;

    for (int x = tid; x < TI * DD; x += 256) {
        int r = x >> 6, d = x & 63;
        qs[x] = g_mq[(size_t)(b * SS + i0 + r) * AH + h * DD + d];
    }
    float gamma = -log1pf(expf(gammas[h]));

    int m4[4];
    float tds[4];
#pragma unroll
    for (int u = 0; u < 4; u++) {
        int j = tid * 4 + u;
        m4[u] = mask[b * SS + j];
        tds[u] = g_tdsm[b * SS + j];
    }
    __syncthreads();

    // ---- scores: s[r][j] = q_r . k_j / 8 ----
    for (int jt = 0; jt < SS / TJ; jt++) {
        const float* kb = g_mk + (size_t)(b * SS + jt * TJ) * AH + h * DD;
        for (int x = tid; x < TJ * 16; x += 256) {
            int row = x >> 4, c4 = x & 15;
            float4 v = *(const float4*)(kb + (size_t)row * AH + c4 * 4);
            float* dst = kt + row * KTS + c4 * 4;
            dst[0] = v.x; dst[1] = v.y; dst[2] = v.z; dst[3] = v.w;
        }
        __syncthreads();
        float a0 = 0, a1 = 0, a2 = 0, a3 = 0;
#pragma unroll
        for (int dd = 0; dd < DD; dd++) {
            float kv = kt[tid * KTS + dd];
            a0 += kv * qs[0 * DD + dd];
            a1 += kv * qs[1 * DD + dd];
            a2 += kv * qs[2 * DD + dd];
            a3 += kv * qs[3 * DD + dd];
        }
        int j = jt * TJ + tid;
        sbuf[0 * SS + j] = a0 * 0.125f;
        sbuf[1 * SS + j] = a1 * 0.125f;
        sbuf[2 * SS + j] = a2 * 0.125f;
        sbuf[3 * SS + j] = a3 * 0.125f;
        __syncthreads();
    }

    // ---- per-row: softmax -> cumsum -> effect -> softmax(probs) ----
    for (int r = 0; r < TI; r++) {
        float* srow = sbuf + r * SS;
        const int i = i0 + r;
        float sv[4];
        float lmax = -3.0e38f;
#pragma unroll
        for (int u = 0; u < 4; u++) {
            sv[u] = srow[tid * 4 + u];
            float msv = m4[u] ? sv[u] : -1e8f;
            lmax = fmaxf(lmax, msv);
        }
        red[tid] = lmax;
        __syncthreads();
        for (int o = 128; o > 0; o >>= 1) {
            if (tid < o) red[tid] = fmaxf(red[tid], red[tid + o]);
            __syncthreads();
        }
        float rmax = red[0];
        __syncthreads();

        float pv[4], lpre[4], run = 0.f;
#pragma unroll
        for (int u = 0; u < 4; u++) {
            pv[u] = m4[u] ? expf(sv[u] - rmax) : 0.f;
            run += pv[u];
            lpre[u] = run;
        }
        scn[tid] = run;
        __syncthreads();
        float x = run;
        for (int o = 1; o < 256; o <<= 1) {
            float y = (tid >= o) ? scn[tid - o] : 0.f;
            __syncthreads();
            x += y;
            scn[tid] = x;
            __syncthreads();
        }
        float total = scn[255];
        float excl = x - run;
        float invZ = 1.0f / total;

        float ns[4];
        float lmax2 = -3.0e38f;
#pragma unroll
        for (int u = 0; u < 4; u++) {
            int j = tid * 4 + u;
            float cum = excl + lpre[u];
            float pos = fabsf((float)(j - i));
            float dsq = (total - cum) * invZ * pos;
            float dsc = sqrtf(fmaxf(dsq, 0.f));
            float te = expf(dsc * gamma);
            te = fminf(fmaxf(te, 1e-5f), 1e5f);
            float eff = te - ((j < i) ? tds[u] : 0.f);
            ns[u] = m4[u] ? sv[u] * eff : -1e8f;
            lmax2 = fmaxf(lmax2, ns[u]);
        }
        red[tid] = lmax2;
        __syncthreads();
        for (int o = 128; o > 0; o >>= 1) {
            if (tid < o) red[tid] = fmaxf(red[tid], red[tid + o]);
            __syncthreads();
        }
        float rmax2 = red[0];
        __syncthreads();
        float ev[4], lsum = 0.f;
#pragma unroll
        for (int u = 0; u < 4; u++) {
            ev[u] = expf(ns[u] - rmax2);
            lsum += ev[u];
        }
        red[tid] = lsum;
        __syncthreads();
        for (int o = 128; o > 0; o >>= 1) {
            if (tid < o) red[tid] += red[tid + o];
            __syncthreads();
        }
        float inv2 = 1.0f / red[0];
        __syncthreads();
#pragma unroll
        for (int u = 0; u < 4; u++) srow[tid * 4 + u] = ev[u] * inv2;
    }
    __syncthreads();

    // ---- PV: ctx[r][d] = sum_j probs[r][j] * v[j][d] ----
    int g = tid >> 6, d = tid & 63;
    float acc[TI] = {0.f, 0.f, 0.f, 0.f};
    for (int jt = 0; jt < SS / TJ; jt++) {
        const float* vb = g_mv + (size_t)(b * SS + jt * TJ) * AH + h * DD;
        for (int x = tid; x < TJ * 16; x += 256) {
            int row = x >> 4, c4 = x & 15;
            float4 v = *(const float4*)(vb + (size_t)row * AH + c4 * 4);
            float* dst = kt + row * KTS + c4 * 4;
            dst[0] = v.x; dst[1] = v.y; dst[2] = v.z; dst[3] = v.w;
        }
        __syncthreads();
#pragma unroll 4
        for (int jj0 = 0; jj0 < 64; jj0++) {
            int jj = g * 64 + jj0;
            float vv = kt[jj * KTS + d];
            const float* sp = sbuf + jt * TJ + jj;
            acc[0] += sp[0 * SS] * vv;
            acc[1] += sp[1 * SS] * vv;
            acc[2] += sp[2 * SS] * vv;
            acc[3] += sp[3 * SS] * vv;
        }
        __syncthreads();
    }
#pragma unroll
    for (int r = 0; r < TI; r++) {
        cbuf[tid] = acc[r];
        __syncthreads();
        if (g == 0) {
            float v = cbuf[d] + cbuf[64 + d] + cbuf[128 + d] + cbuf[192 + d];
            out[(size_t)(b * SS + i0 + r) * (2 * AH) + h * DD + d] = v;
        }
        __syncthreads();
    }
}

// ---------------- host launcher ----------------
extern "C" void kernel_launch(void* const* d_in, const int* in_sizes, int n_in,
                              void* d_out, int out_size) {
    const float* Q = (const float*)d_in[0];
    const float* K = (const float*)d_in[1];
    const float* V = (const float*)d_in[2];
    const float* td = (const float*)d_in[3];
    const int* mask = (const int*)d_in[4];
    const float* Wq = (const float*)d_in[5];
    const float* Wk = (const float*)d_in[6];
    const float* Wv = (const float*)d_in[7];
    const float* dw_w = (const float*)d_in[8];
    const float* pw_w = (const float*)d_in[9];
    const float* sep_b = (const float*)d_in[10];
    const float* ck_W = (const float*)d_in[11];
    const float* ck_b = (const float*)d_in[12];
    const float* co_W = (const float*)d_in[13];
    const float* co_b = (const float*)d_in[14];
    const float* gammas = (const float*)d_in[15];
    float* out = (float*)d_out;

    float *p_mq, *p_mk, *p_mv, *p_co, *p_mkc, *p_dw, *p_pwT;
    cudaGetSymbolAddress((void**)&p_mq, g_mq);
    cudaGetSymbolAddress((void**)&p_mk, g_mk);
    cudaGetSymbolAddress((void**)&p_mv, g_mv);
    cudaGetSymbolAddress((void**)&p_co, g_co);
    cudaGetSymbolAddress((void**)&p_mkc, g_mkc);
    cudaGetSymbolAddress((void**)&p_dw, g_dw);
    cudaGetSymbolAddress((void**)&p_pwT, g_pwT);

    const int smem_attn = (TJ * KTS + TI * SS + TI * DD + 256 * 3) * 4;
    cudaFuncSetAttribute(attn_kernel, cudaFuncAttributeMaxDynamicSharedMemorySize, smem_attn);

    // 1) transpose pw_w, depthwise conv
    transpose_pw_kernel<<<(AH * HID + 255) / 256, 256>>>(pw_w);
    dw_kernel<<<(MROWS * HID + 255) / 256, 256>>>(K, dw_w);

    // 2) projections + pointwise conv GEMMs
    dim3 gg(AH / 64, MROWS / 64);
    sgemm_kernel<<<gg, 256>>>(Q, Wq, nullptr, p_mq, MROWS, AH, HID);
    sgemm_kernel<<<gg, 256>>>(K, Wk, nullptr, p_mk, MROWS, AH, HID);
    sgemm_kernel<<<gg, 256>>>(V, Wv, nullptr, p_mv, MROWS, AH, HID);
    sgemm_kernel<<<gg, 256>>>(V, co_W, co_b, p_co, MROWS, AH, HID);
    sgemm_kernel<<<gg, 256>>>(p_dw, p_pwT, sep_b, p_mkc, MROWS, AH, HID);

    // 3) dynamic conv path
    ck_kernel<<<MROWS, 64>>>(ck_W, ck_b);
    convout_kernel<<<(BB * SS * HH * DD + 255) / 256, 256>>>(out);

    // 4) td softmax precompute
    tdsm_kernel<<<BB, 256>>>(td, mask);

    // 5) fused attention
    attn_kernel<<<BB * HH * (SS / TI), 256, smem_attn>>>(mask, gammas, out);
}

// round 12
// speedup vs baseline: 1.2868x; 1.2868x over previous
#include <cuda_runtime.h>
#include <math.h>

#define BB 4
#define SS 1024
#define HID 768
#define HH 6
#define DD 64
#define AH 384
#define KSZ 9
#define PADW 4
#define MROWS (BB*SS)

// ---------------- scratch (device globals; no allocation) ----------------
__device__ float g_mq[MROWS*AH];
__device__ float g_mk[MROWS*AH];
__device__ float g_mv[MROWS*AH];
__device__ float g_co[MROWS*AH];
__device__ float g_mkc[MROWS*AH];
__device__ float g_dw[MROWS*HID];
__device__ float g_pwT[HID*AH];
__device__ float g_ck[MROWS*HH*KSZ];
__device__ float g_tdsm[BB*SS];

// ---------------- transpose pw_w (AH,HID) -> (HID,AH) ----------------
__global__ void transpose_pw_kernel(const float* __restrict__ pw) {
    int idx = blockIdx.x * 256 + threadIdx.x;
    if (idx < AH * HID) {
        int o = idx / HID, c = idx % HID;
        g_pwT[c * AH + o] = pw[idx];
    }
}

// ---------------- depthwise conv over sequence dim of K ----------------
__global__ void dw_kernel(const float* __restrict__ Kin, const float* __restrict__ dww) {
    int idx = blockIdx.x * 256 + threadIdx.x;
    if (idx >= MROWS * HID) return;
    int c = idx % HID;
    int m = idx / HID;
    int s = m % SS;
    int b = m / SS;
    float acc = 0.f;
#pragma unroll
    for (int k = 0; k < KSZ; k++) {
        int sp = s + k - PADW;
        if (sp >= 0 && sp < SS)
            acc += Kin[(size_t)(b * SS + sp) * HID + c] * dww[c * KSZ + k];
    }
    g_dw[idx] = acc;
}

// ---------------- SGEMM NN: C[M,N] = A[M,K] @ B[K,N] (+bias) ----------------
__global__ void sgemm_kernel(const float* __restrict__ A, const float* __restrict__ Bm,
                             const float* __restrict__ bias, float* __restrict__ C,
                             int M, int N, int Kd) {
    __shared__ float As[16][64];
    __shared__ float Bs[16][64];
    int tid = threadIdx.x;
    int tx = tid & 15, ty = tid >> 4;
    int n0 = blockIdx.x * 64, m0 = blockIdx.y * 64;
    int arow = tid >> 2, ak4 = tid & 3;
    int bk = tid >> 4, bc4 = tid & 15;
    float acc[4][4];
#pragma unroll
    for (int i = 0; i < 4; i++)
#pragma unroll
        for (int j = 0; j < 4; j++) acc[i][j] = 0.f;

    for (int k0 = 0; k0 < Kd; k0 += 16) {
        float4 av = *(const float4*)(A + (size_t)(m0 + arow) * Kd + k0 + ak4 * 4);
        As[ak4 * 4 + 0][arow] = av.x;
        As[ak4 * 4 + 1][arow] = av.y;
        As[ak4 * 4 + 2][arow] = av.z;
        As[ak4 * 4 + 3][arow] = av.w;
        float4 bv = *(const float4*)(Bm + (size_t)(k0 + bk) * N + n0 + bc4 * 4);
        *(float4*)&Bs[bk][bc4 * 4] = bv;
        __syncthreads();
#pragma unroll
        for (int kk = 0; kk < 16; kk++) {
            float a[4], bb[4];
#pragma unroll
            for (int i = 0; i < 4; i++) a[i] = As[kk][ty * 4 + i];
#pragma unroll
            for (int j = 0; j < 4; j++) bb[j] = Bs[kk][tx * 4 + j];
#pragma unroll
            for (int i = 0; i < 4; i++)
#pragma unroll
                for (int j = 0; j < 4; j++) acc[i][j] += a[i] * bb[j];
        }
        __syncthreads();
    }
#pragma unroll
    for (int i = 0; i < 4; i++) {
        int row = m0 + ty * 4 + i;
#pragma unroll
        for (int j = 0; j < 4; j++) {
            int col = n0 + tx * 4 + j;
            float v = acc[i][j];
            if (bias) v += bias[col];
            C[(size_t)row * N + col] = v;
        }
    }
}

// ---------------- ck = softmax over KS of (mkc*mq) @ ck_W + ck_b ----------------
__global__ void ck_kernel(const float* __restrict__ ckW, const float* __restrict__ ckb) {
    __shared__ float arow[AH];
    __shared__ float lg[HH * KSZ];
    int m = blockIdx.x;
    int tid = threadIdx.x; // 64 threads
    for (int x = tid; x < AH; x += 64)
        arow[x] = g_mkc[(size_t)m * AH + x] * g_mq[(size_t)m * AH + x];
    __syncthreads();
    if (tid < HH * KSZ) {
        float acc = ckb[tid];
        for (int c = 0; c < AH; c++) acc += arow[c] * ckW[c * (HH * KSZ) + tid];
        lg[tid] = acc;
    }
    __syncthreads();
    if (tid < HH) {
        float mx = -3.0e38f;
#pragma unroll
        for (int k = 0; k < KSZ; k++) mx = fmaxf(mx, lg[tid * KSZ + k]);
        float e[KSZ], sum = 0.f;
#pragma unroll
        for (int k = 0; k < KSZ; k++) { e[k] = expf(lg[tid * KSZ + k] - mx); sum += e[k]; }
        float inv = 1.0f / sum;
#pragma unroll
        for (int k = 0; k < KSZ; k++)
            g_ck[(size_t)m * (HH * KSZ) + tid * KSZ + k] = e[k] * inv;
    }
}

// ---------------- conv_out: dynamic-kernel gather over co ----------------
__global__ void convout_kernel(float* __restrict__ out) {
    int idx = blockIdx.x * 256 + threadIdx.x;
    if (idx >= BB * SS * HH * DD) return;
    int d = idx & 63;
    int h = (idx >> 6) % HH;
    int s = (idx / (DD * HH)) % SS;
    int b = idx / (DD * HH * SS);
    const float* ckp = g_ck + ((size_t)(b * SS + s) * HH + h) * KSZ;
    float acc = 0.f;
#pragma unroll
    for (int k = 0; k < KSZ; k++) {
        int sp = s + k - PADW;
        if (sp >= 0 && sp < SS)
            acc += g_co[(size_t)(b * SS + sp) * AH + h * DD + d] * ckp[k];
    }
    out[(size_t)(b * SS + s) * (2 * AH) + AH + h * DD + d] = acc;
}

// ---------------- td_sm precompute (per batch) ----------------
__global__ void tdsm_kernel(const float* __restrict__ td, const int* __restrict__ mask) {
    __shared__ float red[256];
    int b = blockIdx.x;
    int tid = threadIdx.x;
    float tv[4];
    float ssq = 0.f;
#pragma unroll
    for (int u = 0; u < 4; u++) {
        tv[u] = td[b * SS + tid * 4 + u];
        ssq += tv[u] * tv[u];
    }
    red[tid] = ssq;
    __syncthreads();
    for (int o = 128; o > 0; o >>= 1) {
        if (tid < o) red[tid] += red[tid + o];
        __syncthreads();
    }
    float denom = fmaxf(sqrtf(red[0]), 1e-12f);
    __syncthreads();
    int ms[4];
    float mv[4];
    float lmax = -3.0e38f;
#pragma unroll
    for (int u = 0; u < 4; u++) {
        ms[u] = mask[b * SS + tid * 4 + u];
        mv[u] = ms[u] ? (tv[u] / denom) : -1e4f;
        lmax = fmaxf(lmax, mv[u]);
    }
    red[tid] = lmax;
    __syncthreads();
    for (int o = 128; o > 0; o >>= 1) {
        if (tid < o) red[tid] = fmaxf(red[tid], red[tid + o]);
        __syncthreads();
    }
    float rmax = red[0];
    __syncthreads();
    float e[4], lsum = 0.f;
#pragma unroll
    for (int u = 0; u < 4; u++) {
        e[u] = ms[u] ? expf(mv[u] - rmax) : 0.f;
        lsum += e[u];
    }
    red[tid] = lsum;
    __syncthreads();
    for (int o = 128; o > 0; o >>= 1) {
        if (tid < o) red[tid] += red[tid + o];
        __syncthreads();
    }
    float invZ = 1.0f / red[0];
#pragma unroll
    for (int u = 0; u < 4; u++)
        g_tdsm[b * SS + tid * 4 + u] = e[u] * invZ;
}

// ---------------- fused attention v2.1 ----------------
// TI=16 rows/block, 256 threads. Warp-owned rows in the middle phase (shfl
// scan/reduce, no block barriers). 4x4 register micro-tiles in QK^T and PV.
// Staging uses SCALAR smem stores: KTS=65 rows are only 4B-aligned, and the
// odd stride is required for conflict-free reads in the FMA loops.
#define TI2 16
#define TJ2 256
#define KTS 65       // kt row stride (conflict-free; NOT float4-alignable)
#define SROW 1025    // sbuf row stride (conflict-free row access)

__global__ __launch_bounds__(256, 1)
void attn_kernel(const int* __restrict__ mask, const float* __restrict__ gammas,
                 float* __restrict__ out) {
    extern __shared__ float sm[];
    float* kt   = sm;                      // 256*65      = 16640
    float* sbuf = kt + TJ2 * KTS;          // 16*1025     = 16400
    float* qs   = sbuf + TI2 * SROW;       // 16*64       = 1024
    float* cbuf = qs + TI2 * DD;           // 4*16*65     = 4160
    float* tds_s = cbuf + 4 * TI2 * 65;    // 1024
    int*   msk_s = (int*)(tds_s + SS);     // 1024

    const int tid = threadIdx.x;
    const int i0 = blockIdx.x * TI2;
    const int bh = blockIdx.y;
    const int h = bh % HH;
    const int b = bh / HH;

    // stage q rows, mask, tdsm
    for (int x = tid; x < TI2 * DD; x += 256) {
        int r = x >> 6, d = x & 63;
        qs[x] = g_mq[(size_t)(b * SS + i0 + r) * AH + h * DD + d];
    }
    for (int j = tid; j < SS; j += 256) {
        msk_s[j] = mask[b * SS + j];
        tds_s[j] = g_tdsm[b * SS + j];
    }
    const float gamma = -log1pf(expf(gammas[h]));
    __syncthreads();

    // ================= scores: s[r][j] = q_r . k_j / 8 =================
    {
        const int jq = tid & 63;   // j = jq + u*64 within tile
        const int rg = tid >> 6;   // rows rg*4 + v
        for (int jt = 0; jt < SS / TJ2; jt++) {
            const float* kb = g_mk + (size_t)(b * SS + jt * TJ2) * AH + h * DD;
            for (int x = tid; x < TJ2 * 16; x += 256) {
                int row = x >> 4, c4 = x & 15;
                float4 v = *(const float4*)(kb + (size_t)row * AH + c4 * 4);
                float* dst = kt + row * KTS + c4 * 4;   // 4B-aligned only
                dst[0] = v.x; dst[1] = v.y; dst[2] = v.z; dst[3] = v.w;
            }
            __syncthreads();
            float acc[4][4];
#pragma unroll
            for (int v = 0; v < 4; v++)
#pragma unroll
                for (int u = 0; u < 4; u++) acc[v][u] = 0.f;
#pragma unroll 8
            for (int dd = 0; dd < DD; dd++) {
                float kv[4], qv[4];
#pragma unroll
                for (int u = 0; u < 4; u++) kv[u] = kt[(jq + u * 64) * KTS + dd];
#pragma unroll
                for (int v = 0; v < 4; v++) qv[v] = qs[(rg * 4 + v) * DD + dd];
#pragma unroll
                for (int v = 0; v < 4; v++)
#pragma unroll
                    for (int u = 0; u < 4; u++) acc[v][u] += kv[u] * qv[v];
            }
#pragma unroll
            for (int v = 0; v < 4; v++)
#pragma unroll
                for (int u = 0; u < 4; u++)
                    sbuf[(rg * 4 + v) * SROW + jt * TJ2 + jq + u * 64] = acc[v][u] * 0.125f;
            __syncthreads();
        }
    }

    // ================= middle: per-row softmax -> cumsum -> effect -> softmax ===
    // warp w owns rows 2w and 2w+1; row element j = t*32 + lane held in regs
    {
        const int lane = tid & 31;
        const int w = tid >> 5;
        for (int rr = 0; rr < 2; rr++) {
            const int r = w * 2 + rr;
            const int i = i0 + r;
            float* srow = sbuf + r * SROW;

            float sv[32];
            unsigned mbits = 0;
            float lmax = -3.0e38f;
#pragma unroll
            for (int t = 0; t < 32; t++) {
                int j = t * 32 + lane;
                sv[t] = srow[j];
                if (msk_s[j]) {
                    mbits |= (1u << t);
                    lmax = fmaxf(lmax, sv[t]);
                }
            }
#pragma unroll
            for (int o = 16; o > 0; o >>= 1)
                lmax = fmaxf(lmax, __shfl_xor_sync(0xffffffffu, lmax, o));

            // p = exp, inclusive cumsum over j (scan within t, carry across t)
            float cum[32];
            float carry = 0.f;
#pragma unroll
            for (int t = 0; t < 32; t++) {
                float p = (mbits >> t & 1u) ? expf(sv[t] - lmax) : 0.f;
                float x = p;
#pragma unroll
                for (int o = 1; o < 32; o <<= 1) {
                    float y = __shfl_up_sync(0xffffffffu, x, o);
                    if (lane >= o) x += y;
                }
                cum[t] = carry + x;
                carry += __shfl_sync(0xffffffffu, x, 31);
            }
            const float total = carry;
            const float invZ = 1.0f / total;

            float lmax2 = -3.0e38f;
#pragma unroll
            for (int t = 0; t < 32; t++) {
                int j = t * 32 + lane;
                float pos = fabsf((float)(j - i));
                float dsq = (total - cum[t]) * invZ * pos;
                float te = expf(sqrtf(fmaxf(dsq, 0.f)) * gamma);
                te = fminf(fmaxf(te, 1e-5f), 1e5f);
                float eff = te - ((j < i) ? tds_s[j] : 0.f);
                float ns = (mbits >> t & 1u) ? sv[t] * eff : -1e8f;
                sv[t] = ns;
                lmax2 = fmaxf(lmax2, ns);
            }
#pragma unroll
            for (int o = 16; o > 0; o >>= 1)
                lmax2 = fmaxf(lmax2, __shfl_xor_sync(0xffffffffu, lmax2, o));

            float lsum = 0.f;
#pragma unroll
            for (int t = 0; t < 32; t++) {
                sv[t] = expf(sv[t] - lmax2);
                lsum += sv[t];
            }
#pragma unroll
            for (int o = 16; o > 0; o >>= 1)
                lsum += __shfl_xor_sync(0xffffffffu, lsum, o);
            const float inv2 = 1.0f / lsum;
#pragma unroll
            for (int t = 0; t < 32; t++)
                srow[t * 32 + lane] = sv[t] * inv2;
        }
    }
    __syncthreads();

    // ================= PV: ctx[r][d] = sum_j probs[r][j] * v[j][d] =================
    {
        const int dq = tid & 15;          // d = dq + u*16
        const int rg = (tid >> 4) & 3;    // rows rg*4 + v
        const int js = tid >> 6;          // j chunk [js*64, js*64+64)
        float pacc[4][4];
#pragma unroll
        for (int v = 0; v < 4; v++)
#pragma unroll
            for (int u = 0; u < 4; u++) pacc[v][u] = 0.f;

        for (int jt = 0; jt < SS / TJ2; jt++) {
            const float* vb = g_mv + (size_t)(b * SS + jt * TJ2) * AH + h * DD;
            for (int x = tid; x < TJ2 * 16; x += 256) {
                int row = x >> 4, c4 = x & 15;
                float4 v = *(const float4*)(vb + (size_t)row * AH + c4 * 4);
                float* dst = kt + row * KTS + c4 * 4;   // 4B-aligned only
                dst[0] = v.x; dst[1] = v.y; dst[2] = v.z; dst[3] = v.w;
            }
            __syncthreads();
#pragma unroll 8
            for (int jj = 0; jj < 64; jj++) {
                int j = js * 64 + jj;
                float pr[4], vv[4];
#pragma unroll
                for (int v = 0; v < 4; v++) pr[v] = sbuf[(rg * 4 + v) * SROW + jt * TJ2 + j];
#pragma unroll
                for (int u = 0; u < 4; u++) vv[u] = kt[j * KTS + dq + u * 16];
#pragma unroll
                for (int v = 0; v < 4; v++)
#pragma unroll
                    for (int u = 0; u < 4; u++) pacc[v][u] += pr[v] * vv[u];
            }
            __syncthreads();
        }
#pragma unroll
        for (int v = 0; v < 4; v++)
#pragma unroll
            for (int u = 0; u < 4; u++)
                cbuf[js * (TI2 * 65) + (rg * 4 + v) * 65 + dq + u * 16] = pacc[v][u];
    }
    __syncthreads();

    for (int e = tid; e < TI2 * DD; e += 256) {
        int r = e >> 6, d = e & 63;
        float s = cbuf[0 * (TI2 * 65) + r * 65 + d]
                + cbuf[1 * (TI2 * 65) + r * 65 + d]
                + cbuf[2 * (TI2 * 65) + r * 65 + d]
                + cbuf[3 * (TI2 * 65) + r * 65 + d];
        out[(size_t)(b * SS + i0 + r) * (2 * AH) + h * DD + d] = s;
    }
}

// ---------------- host launcher ----------------
extern "C" void kernel_launch(void* const* d_in, const int* in_sizes, int n_in,
                              void* d_out, int out_size) {
    const float* Q = (const float*)d_in[0];
    const float* K = (const float*)d_in[1];
    const float* V = (const float*)d_in[2];
    const float* td = (const float*)d_in[3];
    const int* mask = (const int*)d_in[4];
    const float* Wq = (const float*)d_in[5];
    const float* Wk = (const float*)d_in[6];
    const float* Wv = (const float*)d_in[7];
    const float* dw_w = (const float*)d_in[8];
    const float* pw_w = (const float*)d_in[9];
    const float* sep_b = (const float*)d_in[10];
    const float* ck_W = (const float*)d_in[11];
    const float* ck_b = (const float*)d_in[12];
    const float* co_W = (const float*)d_in[13];
    const float* co_b = (const float*)d_in[14];
    const float* gammas = (const float*)d_in[15];
    float* out = (float*)d_out;

    float *p_mq, *p_mk, *p_mv, *p_co, *p_mkc, *p_dw, *p_pwT;
    cudaGetSymbolAddress((void**)&p_mq, g_mq);
    cudaGetSymbolAddress((void**)&p_mk, g_mk);
    cudaGetSymbolAddress((void**)&p_mv, g_mv);
    cudaGetSymbolAddress((void**)&p_co, g_co);
    cudaGetSymbolAddress((void**)&p_mkc, g_mkc);
    cudaGetSymbolAddress((void**)&p_dw, g_dw);
    cudaGetSymbolAddress((void**)&p_pwT, g_pwT);

    const int smem_attn = (TJ2 * KTS + TI2 * SROW + TI2 * DD + 4 * TI2 * 65 + SS) * 4
                        + SS * (int)sizeof(int);
    cudaFuncSetAttribute(attn_kernel, cudaFuncAttributeMaxDynamicSharedMemorySize, smem_attn);

    // 1) transpose pw_w, depthwise conv
    transpose_pw_kernel<<<(AH * HID + 255) / 256, 256>>>(pw_w);
    dw_kernel<<<(MROWS * HID + 255) / 256, 256>>>(K, dw_w);

    // 2) projections + pointwise conv GEMMs
    dim3 gg(AH / 64, MROWS / 64);
    sgemm_kernel<<<gg, 256>>>(Q, Wq, nullptr, p_mq, MROWS, AH, HID);
    sgemm_kernel<<<gg, 256>>>(K, Wk, nullptr, p_mk, MROWS, AH, HID);
    sgemm_kernel<<<gg, 256>>>(V, Wv, nullptr, p_mv, MROWS, AH, HID);
    sgemm_kernel<<<gg, 256>>>(V, co_W, co_b, p_co, MROWS, AH, HID);
    sgemm_kernel<<<gg, 256>>>(p_dw, p_pwT, sep_b, p_mkc, MROWS, AH, HID);

    // 3) dynamic conv path
    ck_kernel<<<MROWS, 64>>>(ck_W, ck_b);
    convout_kernel<<<(BB * SS * HH * DD + 255) / 256, 256>>>(out);

    // 4) td softmax precompute
    tdsm_kernel<<<BB, 256>>>(td, mask);

    // 5) fused attention v2.1
    dim3 ga(SS / TI2, BB * HH);
    attn_kernel<<<ga, 256, smem_attn>>>(mask, gammas, out);
}

// round 17
// speedup vs baseline: 1.3662x; 1.0617x over previous
#include <cuda_runtime.h>
#include <math.h>

#define BB 4
#define SS 1024
#define HID 768
#define HH 6
#define DD 64
#define AH 384
#define KSZ 9
#define PADW 4
#define MROWS (BB*SS)

// ---------------- scratch (device globals; no allocation) ----------------
__device__ float g_mq[MROWS*AH];
__device__ float g_mk[MROWS*AH];
__device__ float g_mv[MROWS*AH];
__device__ float g_co[MROWS*AH];
__device__ float g_mkc[MROWS*AH];
__device__ float g_dw[MROWS*HID];
__device__ float g_pwT[HID*AH];
__device__ float g_ck[MROWS*HH*KSZ];
__device__ float g_tdsm[BB*SS];

// ---------------- f32x2 packed-math helpers ----------------
__device__ __forceinline__ unsigned long long dup_f32x2(float a) {
    unsigned long long r;
    asm("mov.b64 %0, {%1, %1};" : "=l"(r) : "f"(a));
    return r;
}
__device__ __forceinline__ unsigned long long ffma2(unsigned long long a,
                                                    unsigned long long b,
                                                    unsigned long long c) {
    unsigned long long d;
    asm("fma.rn.f32x2 %0, %1, %2, %3;" : "=l"(d) : "l"(a), "l"(b), "l"(c));
    return d;
}

// ---------------- transpose pw_w (AH,HID) -> (HID,AH) ----------------
__global__ void transpose_pw_kernel(const float* __restrict__ pw) {
    int idx = blockIdx.x * 256 + threadIdx.x;
    if (idx < AH * HID) {
        int o = idx / HID, c = idx % HID;
        g_pwT[c * AH + o] = pw[idx];
    }
}

// ---------------- depthwise conv over sequence dim of K ----------------
__global__ void dw_kernel(const float* __restrict__ Kin, const float* __restrict__ dww) {
    int idx = blockIdx.x * 256 + threadIdx.x;
    if (idx >= MROWS * HID) return;
    int c = idx % HID;
    int m = idx / HID;
    int s = m % SS;
    int b = m / SS;
    float acc = 0.f;
#pragma unroll
    for (int k = 0; k < KSZ; k++) {
        int sp = s + k - PADW;
        if (sp >= 0 && sp < SS)
            acc += Kin[(size_t)(b * SS + sp) * HID + c] * dww[c * KSZ + k];
    }
    g_dw[idx] = acc;
}

// ---------------- batched f32x2 SGEMM: 5 GEMMs, C = A@B (+bias) ----------------
// All shapes M=4096, N=384, K=768. 128x128 block tile, BK=16, 256 threads,
// 8x8 per-thread micro-tile on packed f32x2 accumulators.
struct GemmBatch {
    const float* A[5];
    const float* B[5];
    const float* bias[5];
    float* C[5];
};

#define GBM 128
#define GBN 128
#define GBK 16

__global__ __launch_bounds__(256, 2)
void sgemm5_kernel(GemmBatch p) {
    __shared__ float As[GBK][GBM];
    __shared__ float Bs[GBK][GBN];

    const int g = blockIdx.z;
    const float* __restrict__ A = p.A[g];
    const float* __restrict__ Bm = p.B[g];
    const float* __restrict__ bias = p.bias[g];
    float* __restrict__ C = p.C[g];

    const int tid = threadIdx.x;
    const int tx = tid & 15, ty = tid >> 4;
    const int n0 = blockIdx.x * GBN, m0 = blockIdx.y * GBM;

    // A staging: idx = tid*2+l -> arow = idx>>2 (0..127), ac4 = idx&3
    // B staging: idx = tid*2+l -> brow = idx>>5 (0..15),  bc4 = idx&31
    const int a_row0 = (tid * 2) >> 2,     a_c40 = (tid * 2) & 3;
    const int a_row1 = (tid * 2 + 1) >> 2, a_c41 = (tid * 2 + 1) & 3;
    const int b_row0 = (tid * 2) >> 5,     b_c40 = (tid * 2) & 31;
    const int b_row1 = (tid * 2 + 1) >> 5, b_c41 = (tid * 2 + 1) & 31;

    unsigned long long acc2[8][4];
#pragma unroll
    for (int i = 0; i < 8; i++)
#pragma unroll
        for (int jp = 0; jp < 4; jp++) acc2[i][jp] = 0ull;

    // prefetch k0 = 0
    float4 pa0 = *(const float4*)(A + (size_t)(m0 + a_row0) * HID + a_c40 * 4);
    float4 pa1 = *(const float4*)(A + (size_t)(m0 + a_row1) * HID + a_c41 * 4);
    float4 pb0 = *(const float4*)(Bm + (size_t)b_row0 * AH + n0 + b_c40 * 4);
    float4 pb1 = *(const float4*)(Bm + (size_t)b_row1 * AH + n0 + b_c41 * 4);

    for (int k0 = 0; k0 < HID; k0 += GBK) {
        // store staged tile to smem
        As[a_c40 * 4 + 0][a_row0] = pa0.x;
        As[a_c40 * 4 + 1][a_row0] = pa0.y;
        As[a_c40 * 4 + 2][a_row0] = pa0.z;
        As[a_c40 * 4 + 3][a_row0] = pa0.w;
        As[a_c41 * 4 + 0][a_row1] = pa1.x;
        As[a_c41 * 4 + 1][a_row1] = pa1.y;
        As[a_c41 * 4 + 2][a_row1] = pa1.z;
        As[a_c41 * 4 + 3][a_row1] = pa1.w;
        *(float4*)&Bs[b_row0][b_c40 * 4] = pb0;
        *(float4*)&Bs[b_row1][b_c41 * 4] = pb1;
        __syncthreads();

        // prefetch next tile
        if (k0 + GBK < HID) {
            const int kn = k0 + GBK;
            pa0 = *(const float4*)(A + (size_t)(m0 + a_row0) * HID + kn + a_c40 * 4);
            pa1 = *(const float4*)(A + (size_t)(m0 + a_row1) * HID + kn + a_c41 * 4);
            pb0 = *(const float4*)(Bm + (size_t)(kn + b_row0) * AH + n0 + b_c40 * 4);
            pb1 = *(const float4*)(Bm + (size_t)(kn + b_row1) * AH + n0 + b_c41 * 4);
        }

        // compute
#pragma unroll
        for (int kk = 0; kk < GBK; kk++) {
            float4 av0 = *(const float4*)&As[kk][ty * 8];
            float4 av1 = *(const float4*)&As[kk][ty * 8 + 4];
            ulonglong2 bv0 = *(const ulonglong2*)&Bs[kk][tx * 8];
            ulonglong2 bv1 = *(const ulonglong2*)&Bs[kk][tx * 8 + 4];
            unsigned long long bp[4] = {bv0.x, bv0.y, bv1.x, bv1.y};
            unsigned long long ad[8];
            ad[0] = dup_f32x2(av0.x); ad[1] = dup_f32x2(av0.y);
            ad[2] = dup_f32x2(av0.z); ad[3] = dup_f32x2(av0.w);
            ad[4] = dup_f32x2(av1.x); ad[5] = dup_f32x2(av1.y);
            ad[6] = dup_f32x2(av1.z); ad[7] = dup_f32x2(av1.w);
#pragma unroll
            for (int i = 0; i < 8; i++)
#pragma unroll
                for (int jp = 0; jp < 4; jp++)
                    acc2[i][jp] = ffma2(ad[i], bp[jp], acc2[i][jp]);
        }
        __syncthreads();
    }

    // epilogue
#pragma unroll
    for (int i = 0; i < 8; i++) {
        const int row = m0 + ty * 8 + i;
        float* crow = C + (size_t)row * AH + n0 + tx * 8;
#pragma unroll
        for (int jp = 0; jp < 4; jp++) {
            float2 v = *(float2*)&acc2[i][jp];
            if (bias) {
                v.x += bias[n0 + tx * 8 + jp * 2 + 0];
                v.y += bias[n0 + tx * 8 + jp * 2 + 1];
            }
            *(float2*)(crow + jp * 2) = v;
        }
    }
}

// ---------------- ck = softmax over KS of (mkc*mq) @ ck_W + ck_b ----------------
__global__ void ck_kernel(const float* __restrict__ ckW, const float* __restrict__ ckb) {
    __shared__ float arow[AH];
    __shared__ float lg[HH * KSZ];
    int m = blockIdx.x;
    int tid = threadIdx.x; // 64 threads
    for (int x = tid; x < AH; x += 64)
        arow[x] = g_mkc[(size_t)m * AH + x] * g_mq[(size_t)m * AH + x];
    __syncthreads();
    if (tid < HH * KSZ) {
        float acc = ckb[tid];
        for (int c = 0; c < AH; c++) acc += arow[c] * ckW[c * (HH * KSZ) + tid];
        lg[tid] = acc;
    }
    __syncthreads();
    if (tid < HH) {
        float mx = -3.0e38f;
#pragma unroll
        for (int k = 0; k < KSZ; k++) mx = fmaxf(mx, lg[tid * KSZ + k]);
        float e[KSZ], sum = 0.f;
#pragma unroll
        for (int k = 0; k < KSZ; k++) { e[k] = expf(lg[tid * KSZ + k] - mx); sum += e[k]; }
        float inv = 1.0f / sum;
#pragma unroll
        for (int k = 0; k < KSZ; k++)
            g_ck[(size_t)m * (HH * KSZ) + tid * KSZ + k] = e[k] * inv;
    }
}

// ---------------- conv_out: dynamic-kernel gather over co ----------------
__global__ void convout_kernel(float* __restrict__ out) {
    int idx = blockIdx.x * 256 + threadIdx.x;
    if (idx >= BB * SS * HH * DD) return;
    int d = idx & 63;
    int h = (idx >> 6) % HH;
    int s = (idx / (DD * HH)) % SS;
    int b = idx / (DD * HH * SS);
    const float* ckp = g_ck + ((size_t)(b * SS + s) * HH + h) * KSZ;
    float acc = 0.f;
#pragma unroll
    for (int k = 0; k < KSZ; k++) {
        int sp = s + k - PADW;
        if (sp >= 0 && sp < SS)
            acc += g_co[(size_t)(b * SS + sp) * AH + h * DD + d] * ckp[k];
    }
    out[(size_t)(b * SS + s) * (2 * AH) + AH + h * DD + d] = acc;
}

// ---------------- td_sm precompute (per batch) ----------------
__global__ void tdsm_kernel(const float* __restrict__ td, const int* __restrict__ mask) {
    __shared__ float red[256];
    int b = blockIdx.x;
    int tid = threadIdx.x;
    float tv[4];
    float ssq = 0.f;
#pragma unroll
    for (int u = 0; u < 4; u++) {
        tv[u] = td[b * SS + tid * 4 + u];
        ssq += tv[u] * tv[u];
    }
    red[tid] = ssq;
    __syncthreads();
    for (int o = 128; o > 0; o >>= 1) {
        if (tid < o) red[tid] += red[tid + o];
        __syncthreads();
    }
    float denom = fmaxf(sqrtf(red[0]), 1e-12f);
    __syncthreads();
    int ms[4];
    float mv[4];
    float lmax = -3.0e38f;
#pragma unroll
    for (int u = 0; u < 4; u++) {
        ms[u] = mask[b * SS + tid * 4 + u];
        mv[u] = ms[u] ? (tv[u] / denom) : -1e4f;
        lmax = fmaxf(lmax, mv[u]);
    }
    red[tid] = lmax;
    __syncthreads();
    for (int o = 128; o > 0; o >>= 1) {
        if (tid < o) red[tid] = fmaxf(red[tid], red[tid + o]);
        __syncthreads();
    }
    float rmax = red[0];
    __syncthreads();
    float e[4], lsum = 0.f;
#pragma unroll
    for (int u = 0; u < 4; u++) {
        e[u] = ms[u] ? expf(mv[u] - rmax) : 0.f;
        lsum += e[u];
    }
    red[tid] = lsum;
    __syncthreads();
    for (int o = 128; o > 0; o >>= 1) {
        if (tid < o) red[tid] += red[tid + o];
        __syncthreads();
    }
    float invZ = 1.0f / red[0];
#pragma unroll
    for (int u = 0; u < 4; u++)
        g_tdsm[b * SS + tid * 4 + u] = e[u] * invZ;
}

// ---------------- fused attention v2.1 ----------------
#define TI2 16
#define TJ2 256
#define KTS 65       // kt row stride (conflict-free; NOT float4-alignable)
#define SROW 1025    // sbuf row stride (conflict-free row access)

__global__ __launch_bounds__(256, 1)
void attn_kernel(const int* __restrict__ mask, const float* __restrict__ gammas,
                 float* __restrict__ out) {
    extern __shared__ float sm[];
    float* kt   = sm;                      // 256*65      = 16640
    float* sbuf = kt + TJ2 * KTS;          // 16*1025     = 16400
    float* qs   = sbuf + TI2 * SROW;       // 16*64       = 1024
    float* cbuf = qs + TI2 * DD;           // 4*16*65     = 4160
    float* tds_s = cbuf + 4 * TI2 * 65;    // 1024
    int*   msk_s = (int*)(tds_s + SS);     // 1024

    const int tid = threadIdx.x;
    const int i0 = blockIdx.x * TI2;
    const int bh = blockIdx.y;
    const int h = bh % HH;
    const int b = bh / HH;

    for (int x = tid; x < TI2 * DD; x += 256) {
        int r = x >> 6, d = x & 63;
        qs[x] = g_mq[(size_t)(b * SS + i0 + r) * AH + h * DD + d];
    }
    for (int j = tid; j < SS; j += 256) {
        msk_s[j] = mask[b * SS + j];
        tds_s[j] = g_tdsm[b * SS + j];
    }
    const float gamma = -log1pf(expf(gammas[h]));
    __syncthreads();

    // ================= scores =================
    {
        const int jq = tid & 63;
        const int rg = tid >> 6;
        for (int jt = 0; jt < SS / TJ2; jt++) {
            const float* kb = g_mk + (size_t)(b * SS + jt * TJ2) * AH + h * DD;
            for (int x = tid; x < TJ2 * 16; x += 256) {
                int row = x >> 4, c4 = x & 15;
                float4 v = *(const float4*)(kb + (size_t)row * AH + c4 * 4);
                float* dst = kt + row * KTS + c4 * 4;
                dst[0] = v.x; dst[1] = v.y; dst[2] = v.z; dst[3] = v.w;
            }
            __syncthreads();
            float acc[4][4];
#pragma unroll
            for (int v = 0; v < 4; v++)
#pragma unroll
                for (int u = 0; u < 4; u++) acc[v][u] = 0.f;
#pragma unroll 8
            for (int dd = 0; dd < DD; dd++) {
                float kv[4], qv[4];
#pragma unroll
                for (int u = 0; u < 4; u++) kv[u] = kt[(jq + u * 64) * KTS + dd];
#pragma unroll
                for (int v = 0; v < 4; v++) qv[v] = qs[(rg * 4 + v) * DD + dd];
#pragma unroll
                for (int v = 0; v < 4; v++)
#pragma unroll
                    for (int u = 0; u < 4; u++) acc[v][u] += kv[u] * qv[v];
            }
#pragma unroll
            for (int v = 0; v < 4; v++)
#pragma unroll
                for (int u = 0; u < 4; u++)
                    sbuf[(rg * 4 + v) * SROW + jt * TJ2 + jq + u * 64] = acc[v][u] * 0.125f;
            __syncthreads();
        }
    }

    // ================= middle =================
    {
        const int lane = tid & 31;
        const int w = tid >> 5;
        for (int rr = 0; rr < 2; rr++) {
            const int r = w * 2 + rr;
            const int i = i0 + r;
            float* srow = sbuf + r * SROW;

            float sv[32];
            unsigned mbits = 0;
            float lmax = -3.0e38f;
#pragma unroll
            for (int t = 0; t < 32; t++) {
                int j = t * 32 + lane;
                sv[t] = srow[j];
                if (msk_s[j]) {
                    mbits |= (1u << t);
                    lmax = fmaxf(lmax, sv[t]);
                }
            }
#pragma unroll
            for (int o = 16; o > 0; o >>= 1)
                lmax = fmaxf(lmax, __shfl_xor_sync(0xffffffffu, lmax, o));

            float cum[32];
            float carry = 0.f;
#pragma unroll
            for (int t = 0; t < 32; t++) {
                float p = (mbits >> t & 1u) ? expf(sv[t] - lmax) : 0.f;
                float x = p;
#pragma unroll
                for (int o = 1; o < 32; o <<= 1) {
                    float y = __shfl_up_sync(0xffffffffu, x, o);
                    if (lane >= o) x += y;
                }
                cum[t] = carry + x;
                carry += __shfl_sync(0xffffffffu, x, 31);
            }
            const float total = carry;
            const float invZ = 1.0f / total;

            float lmax2 = -3.0e38f;
#pragma unroll
            for (int t = 0; t < 32; t++) {
                int j = t * 32 + lane;
                float pos = fabsf((float)(j - i));
                float dsq = (total - cum[t]) * invZ * pos;
                float te = expf(sqrtf(fmaxf(dsq, 0.f)) * gamma);
                te = fminf(fmaxf(te, 1e-5f), 1e5f);
                float eff = te - ((j < i) ? tds_s[j] : 0.f);
                float ns = (mbits >> t & 1u) ? sv[t] * eff : -1e8f;
                sv[t] = ns;
                lmax2 = fmaxf(lmax2, ns);
            }
#pragma unroll
            for (int o = 16; o > 0; o >>= 1)
                lmax2 = fmaxf(lmax2, __shfl_xor_sync(0xffffffffu, lmax2, o));

            float lsum = 0.f;
#pragma unroll
            for (int t = 0; t < 32; t++) {
                sv[t] = expf(sv[t] - lmax2);
                lsum += sv[t];
            }
#pragma unroll
            for (int o = 16; o > 0; o >>= 1)
                lsum += __shfl_xor_sync(0xffffffffu, lsum, o);
            const float inv2 = 1.0f / lsum;
#pragma unroll
            for (int t = 0; t < 32; t++)
                srow[t * 32 + lane] = sv[t] * inv2;
        }
    }
    __syncthreads();

    // ================= PV =================
    {
        const int dq = tid & 15;
        const int rg = (tid >> 4) & 3;
        const int js = tid >> 6;
        float pacc[4][4];
#pragma unroll
        for (int v = 0; v < 4; v++)
#pragma unroll
            for (int u = 0; u < 4; u++) pacc[v][u] = 0.f;

        for (int jt = 0; jt < SS / TJ2; jt++) {
            const float* vb = g_mv + (size_t)(b * SS + jt * TJ2) * AH + h * DD;
            for (int x = tid; x < TJ2 * 16; x += 256) {
                int row = x >> 4, c4 = x & 15;
                float4 v = *(const float4*)(vb + (size_t)row * AH + c4 * 4);
                float* dst = kt + row * KTS + c4 * 4;
                dst[0] = v.x; dst[1] = v.y; dst[2] = v.z; dst[3] = v.w;
            }
            __syncthreads();
#pragma unroll 8
            for (int jj = 0; jj < 64; jj++) {
                int j = js * 64 + jj;
                float pr[4], vv[4];
#pragma unroll
                for (int v = 0; v < 4; v++) pr[v] = sbuf[(rg * 4 + v) * SROW + jt * TJ2 + j];
#pragma unroll
                for (int u = 0; u < 4; u++) vv[u] = kt[j * KTS + dq + u * 16];
#pragma unroll
                for (int v = 0; v < 4; v++)
#pragma unroll
                    for (int u = 0; u < 4; u++) pacc[v][u] += pr[v] * vv[u];
            }
            __syncthreads();
        }
#pragma unroll
        for (int v = 0; v < 4; v++)
#pragma unroll
            for (int u = 0; u < 4; u++)
                cbuf[js * (TI2 * 65) + (rg * 4 + v) * 65 + dq + u * 16] = pacc[v][u];
    }
    __syncthreads();

    for (int e = tid; e < TI2 * DD; e += 256) {
        int r = e >> 6, d = e & 63;
        float s = cbuf[0 * (TI2 * 65) + r * 65 + d]
                + cbuf[1 * (TI2 * 65) + r * 65 + d]
                + cbuf[2 * (TI2 * 65) + r * 65 + d]
                + cbuf[3 * (TI2 * 65) + r * 65 + d];
        out[(size_t)(b * SS + i0 + r) * (2 * AH) + h * DD + d] = s;
    }
}

// ---------------- host launcher ----------------
extern "C" void kernel_launch(void* const* d_in, const int* in_sizes, int n_in,
                              void* d_out, int out_size) {
    const float* Q = (const float*)d_in[0];
    const float* K = (const float*)d_in[1];
    const float* V = (const float*)d_in[2];
    const float* td = (const float*)d_in[3];
    const int* mask = (const int*)d_in[4];
    const float* Wq = (const float*)d_in[5];
    const float* Wk = (const float*)d_in[6];
    const float* Wv = (const float*)d_in[7];
    const float* dw_w = (const float*)d_in[8];
    const float* pw_w = (const float*)d_in[9];
    const float* sep_b = (const float*)d_in[10];
    const float* ck_W = (const float*)d_in[11];
    const float* ck_b = (const float*)d_in[12];
    const float* co_W = (const float*)d_in[13];
    const float* co_b = (const float*)d_in[14];
    const float* gammas = (const float*)d_in[15];
    float* out = (float*)d_out;

    float *p_mq, *p_mk, *p_mv, *p_co, *p_mkc, *p_dw, *p_pwT;
    cudaGetSymbolAddress((void**)&p_mq, g_mq);
    cudaGetSymbolAddress((void**)&p_mk, g_mk);
    cudaGetSymbolAddress((void**)&p_mv, g_mv);
    cudaGetSymbolAddress((void**)&p_co, g_co);
    cudaGetSymbolAddress((void**)&p_mkc, g_mkc);
    cudaGetSymbolAddress((void**)&p_dw, g_dw);
    cudaGetSymbolAddress((void**)&p_pwT, g_pwT);

    const int smem_attn = (TJ2 * KTS + TI2 * SROW + TI2 * DD + 4 * TI2 * 65 + SS) * 4
                        + SS * (int)sizeof(int);
    cudaFuncSetAttribute(attn_kernel, cudaFuncAttributeMaxDynamicSharedMemorySize, smem_attn);

    // 1) transpose pw_w, depthwise conv
    transpose_pw_kernel<<<(AH * HID + 255) / 256, 256>>>(pw_w);
    dw_kernel<<<(MROWS * HID + 255) / 256, 256>>>(K, dw_w);

    // 2) all five GEMMs in one batched f32x2 launch
    GemmBatch gb;
    gb.A[0] = Q;    gb.B[0] = Wq;    gb.bias[0] = nullptr; gb.C[0] = p_mq;
    gb.A[1] = K;    gb.B[1] = Wk;    gb.bias[1] = nullptr; gb.C[1] = p_mk;
    gb.A[2] = V;    gb.B[2] = Wv;    gb.bias[2] = nullptr; gb.C[2] = p_mv;
    gb.A[3] = V;    gb.B[3] = co_W;  gb.bias[3] = co_b;    gb.C[3] = p_co;
    gb.A[4] = p_dw; gb.B[4] = p_pwT; gb.bias[4] = sep_b;   gb.C[4] = p_mkc;
    dim3 gg(AH / GBN, MROWS / GBM, 5);
    sgemm5_kernel<<<gg, 256>>>(gb);

    // 3) dynamic conv path
    ck_kernel<<<MROWS, 64>>>(ck_W, ck_b);
    convout_kernel<<<(BB * SS * HH * DD + 255) / 256, 256>>>(out);

    // 4) td softmax precompute
    tdsm_kernel<<<BB, 256>>>(td, mask);

    // 5) fused attention v2.1
    dim3 ga(SS / TI2, BB * HH);
    attn_kernel<<<ga, 256, smem_attn>>>(mask, gammas, out);
}